// round 2
// baseline (speedup 1.0000x reference)
#include <cuda_runtime.h>

// ---------------------------------------------------------------------------
// NeuralLongTermMemory — fp32 SIMT baseline (Round 1)
//   B=4, S=4096 -> N=16384 tokens, D=1024, H=2048
//   12 dense GEMMs chained on one stream, fused epilogues, deterministic
//   gate reduction (per-block partials, fixed-order tree sum).
// ---------------------------------------------------------------------------

constexpr int NTOK = 16384;
constexpr int DIM  = 1024;
constexpr int HID  = 2048;

constexpr int BM = 128, BN = 128, BK = 16, TPB = 256;

// ---- scratch (static device arrays; no allocation at runtime) --------------
__device__ float g_k  [NTOK * DIM];   // 64 MB
__device__ float g_v  [NTOK * DIM];
__device__ float g_q  [NTOK * DIM];
__device__ float g_z  [NTOK * HID];   // 128 MB (z = k@M1^T; reused for zq)
__device__ float g_h  [NTOK * HID];   // 128 MB (silu(z); reused for hq)
__device__ float g_e  [NTOK * DIM];   // (2/D)(pred - v)
__device__ float g_dz [NTOK * HID];
__device__ float g_ret[NTOK * DIM];
__device__ float g_M1n[HID * DIM];
__device__ float g_M2n[DIM * HID];
__device__ float g_part[3 * 1024];    // per-block sigmoid partial sums
__device__ float g_scal[3];           // alpha, theta, eta

// ---- tile loaders -----------------------------------------------------------
// Load a [128 rows][16 k] tile from row-major src (row stride ld) and
// transpose into dst[k][m] (dst row stride BM).
__device__ __forceinline__ void load_transpose(float* __restrict__ dst,
    const float* __restrict__ src, int ld, int tid)
{
#pragma unroll
  for (int p = 0; p < 2; ++p) {
    int r = (tid >> 2) + p * 64;   // m
    int c = (tid & 3) * 4;         // k
    float4 t = *reinterpret_cast<const float4*>(src + (size_t)r * ld + c);
    dst[(c + 0) * BM + r] = t.x;
    dst[(c + 1) * BM + r] = t.y;
    dst[(c + 2) * BM + r] = t.z;
    dst[(c + 3) * BM + r] = t.w;
  }
}

// Load a [16 k rows][128 cols] tile directly into dst[k][col].
__device__ __forceinline__ void load_direct(float* __restrict__ dst,
    const float* __restrict__ src, int ld, int tid)
{
#pragma unroll
  for (int p = 0; p < 2; ++p) {
    int r = (tid >> 5) + p * 8;    // k
    int c = (tid & 31) * 4;        // col
    float4 t = *reinterpret_cast<const float4*>(src + (size_t)r * ld + c);
    *reinterpret_cast<float4*>(dst + r * BM + c) = t;
  }
}

// ---- GEMM core --------------------------------------------------------------
// Computes a 128x128 output tile: acc[i][j] += sum_k a(m,k)*b(n,k)
//   AMODE 0: a(m,k) = A[m*lda + k]  (row-major M x K)
//   AMODE 1: a(m,k) = A[k*lda + m]  (row-major K x M, i.e. A^T)
//   BMODE 0: b(n,k) = B[n*ldb + k]  (row-major N x K, i.e. B^T operand)
//   BMODE 1: b(n,k) = B[k*ldb + n]  (row-major K x N)
template<int AMODE, int BMODE>
__device__ __forceinline__ void gemm_core(const float* __restrict__ A,
    const float* __restrict__ B, int K, int lda, int ldb, float acc[8][8])
{
  __shared__ __align__(16) float As[BK * BM];
  __shared__ __align__(16) float Bs[BK * BN];
  const int tid   = threadIdx.x;
  const int row_t = (tid >> 4) * 8;
  const int col_t = (tid & 15) * 8;

  for (int kt = 0; kt < K; kt += BK) {
    const float* aSrc = (AMODE == 0)
        ? A + (size_t)blockIdx.y * BM * lda + kt
        : A + (size_t)kt * lda + blockIdx.y * BM;
    const float* bSrc = (BMODE == 0)
        ? B + (size_t)blockIdx.x * BN * ldb + kt
        : B + (size_t)kt * ldb + blockIdx.x * BN;
    if (AMODE == 0) load_transpose(As, aSrc, lda, tid);
    else            load_direct  (As, aSrc, lda, tid);
    if (BMODE == 0) load_transpose(Bs, bSrc, ldb, tid);
    else            load_direct  (Bs, bSrc, ldb, tid);
    __syncthreads();
#pragma unroll
    for (int k = 0; k < BK; ++k) {
      float a[8], b[8];
      *reinterpret_cast<float4*>(&a[0]) = *reinterpret_cast<const float4*>(&As[k * BM + row_t]);
      *reinterpret_cast<float4*>(&a[4]) = *reinterpret_cast<const float4*>(&As[k * BM + row_t + 4]);
      *reinterpret_cast<float4*>(&b[0]) = *reinterpret_cast<const float4*>(&Bs[k * BN + col_t]);
      *reinterpret_cast<float4*>(&b[4]) = *reinterpret_cast<const float4*>(&Bs[k * BN + col_t + 4]);
#pragma unroll
      for (int i = 0; i < 8; ++i)
#pragma unroll
        for (int j = 0; j < 8; ++j)
          acc[i][j] = fmaf(a[i], b[j], acc[i][j]);
    }
    __syncthreads();
  }
}

__device__ __forceinline__ float sigmoidf_(float x) { return 1.f / (1.f + expf(-x)); }

// ---- kernels ----------------------------------------------------------------

// C = A @ B^T (plain store)
__global__ void __launch_bounds__(TPB)
k_gemm_nt(const float* __restrict__ A, const float* __restrict__ B,
          float* __restrict__ C, int K, int lda, int ldb, int ldc)
{
  float acc[8][8] = {};
  gemm_core<0, 0>(A, B, K, lda, ldb, acc);
  int r0 = blockIdx.y * BM + (threadIdx.x >> 4) * 8;
  int c0 = blockIdx.x * BN + (threadIdx.x & 15) * 8;
#pragma unroll
  for (int i = 0; i < 8; ++i) {
    float4* p = reinterpret_cast<float4*>(C + (size_t)(r0 + i) * ldc + c0);
    p[0] = make_float4(acc[i][0], acc[i][1], acc[i][2], acc[i][3]);
    p[1] = make_float4(acc[i][4], acc[i][5], acc[i][6], acc[i][7]);
  }
}

// gate: per-block sum of sigmoid(A@B^T + bias) -> partial[block]
__global__ void __launch_bounds__(TPB)
k_gemm_gate(const float* __restrict__ A, const float* __restrict__ B,
            const float* __restrict__ bias, float* __restrict__ partial,
            int K, int lda, int ldb)
{
  float acc[8][8] = {};
  gemm_core<0, 0>(A, B, K, lda, ldb, acc);
  int c0 = blockIdx.x * BN + (threadIdx.x & 15) * 8;
  float s = 0.f;
#pragma unroll
  for (int i = 0; i < 8; ++i)
#pragma unroll
    for (int j = 0; j < 8; ++j)
      s += sigmoidf_(acc[i][j] + bias[c0 + j]);
  __shared__ float red[TPB];
  red[threadIdx.x] = s;
  __syncthreads();
  for (int off = TPB / 2; off > 0; off >>= 1) {
    if (threadIdx.x < off) red[threadIdx.x] += red[threadIdx.x + off];
    __syncthreads();
  }
  if (threadIdx.x == 0)
    partial[blockIdx.y * gridDim.x + blockIdx.x] = red[0];
}

// deterministic gate finalize: scal[g] = mean over N*D of sigmoid values
__global__ void __launch_bounds__(TPB)
k_finalize()
{
  __shared__ float red[TPB];
  for (int g = 0; g < 3; ++g) {
    float s = 0.f;
    for (int i = threadIdx.x; i < 1024; i += TPB) s += g_part[g * 1024 + i];
    red[threadIdx.x] = s;
    __syncthreads();
    for (int off = TPB / 2; off > 0; off >>= 1) {
      if (threadIdx.x < off) red[threadIdx.x] += red[threadIdx.x + off];
      __syncthreads();
    }
    if (threadIdx.x == 0)
      g_scal[g] = red[0] * (1.f / ((float)NTOK * (float)DIM));
    __syncthreads();
  }
}

// Z = A @ B^T ; H = silu(Z)
__global__ void __launch_bounds__(TPB)
k_gemm_silu(const float* __restrict__ A, const float* __restrict__ B,
            float* __restrict__ Z, float* __restrict__ Hs,
            int K, int lda, int ldb, int ldc)
{
  float acc[8][8] = {};
  gemm_core<0, 0>(A, B, K, lda, ldb, acc);
  int r0 = blockIdx.y * BM + (threadIdx.x >> 4) * 8;
  int c0 = blockIdx.x * BN + (threadIdx.x & 15) * 8;
#pragma unroll
  for (int i = 0; i < 8; ++i)
#pragma unroll
    for (int j = 0; j < 8; ++j) {
      size_t idx = (size_t)(r0 + i) * ldc + c0 + j;
      float zv = acc[i][j];
      Z[idx]  = zv;
      Hs[idx] = zv * sigmoidf_(zv);
    }
}

// E = scale * (A @ B^T - V)
__global__ void __launch_bounds__(TPB)
k_gemm_err(const float* __restrict__ A, const float* __restrict__ B,
           const float* __restrict__ V, float* __restrict__ E,
           int K, int lda, int ldb, int ldc, float scale)
{
  float acc[8][8] = {};
  gemm_core<0, 0>(A, B, K, lda, ldb, acc);
  int r0 = blockIdx.y * BM + (threadIdx.x >> 4) * 8;
  int c0 = blockIdx.x * BN + (threadIdx.x & 15) * 8;
#pragma unroll
  for (int i = 0; i < 8; ++i)
#pragma unroll
    for (int j = 0; j < 8; ++j) {
      size_t idx = (size_t)(r0 + i) * ldc + c0 + j;
      E[idx] = scale * (acc[i][j] - V[idx]);
    }
}

// DZ = (A @ B) * silu'(Z)      (NN: B row-major K x N)
__global__ void __launch_bounds__(TPB)
k_gemm_dz(const float* __restrict__ A, const float* __restrict__ B,
          const float* __restrict__ Z, float* __restrict__ DZ,
          int K, int lda, int ldb, int ldc)
{
  float acc[8][8] = {};
  gemm_core<0, 1>(A, B, K, lda, ldb, acc);
  int r0 = blockIdx.y * BM + (threadIdx.x >> 4) * 8;
  int c0 = blockIdx.x * BN + (threadIdx.x & 15) * 8;
#pragma unroll
  for (int i = 0; i < 8; ++i)
#pragma unroll
    for (int j = 0; j < 8; ++j) {
      size_t idx = (size_t)(r0 + i) * ldc + c0 + j;
      float zv = Z[idx];
      float sg = sigmoidf_(zv);
      DZ[idx] = acc[i][j] * (sg * (1.f + zv * (1.f - sg)));
    }
}

// G = A^T @ B ; Mnew = (1-alpha)*Mold + eta*Sold - theta*G   (TN)
__global__ void __launch_bounds__(TPB)
k_gemm_upd(const float* __restrict__ A, const float* __restrict__ B,
           const float* __restrict__ Mold, const float* __restrict__ Sold,
           float* __restrict__ Mnew, int K, int lda, int ldb, int ldc)
{
  float acc[8][8] = {};
  gemm_core<1, 1>(A, B, K, lda, ldb, acc);
  float al = g_scal[0], th = g_scal[1], et = g_scal[2];
  int r0 = blockIdx.y * BM + (threadIdx.x >> 4) * 8;
  int c0 = blockIdx.x * BN + (threadIdx.x & 15) * 8;
#pragma unroll
  for (int i = 0; i < 8; ++i)
#pragma unroll
    for (int j = 0; j < 8; ++j) {
      size_t idx = (size_t)(r0 + i) * ldc + c0 + j;
      Mnew[idx] = (1.f - al) * Mold[idx] + et * Sold[idx] - th * acc[i][j];
    }
}

// ---- launch ------------------------------------------------------------------
extern "C" void kernel_launch(void* const* d_in, const int* in_sizes, int n_in,
                              void* d_out, int out_size)
{
  (void)in_sizes; (void)n_in; (void)out_size;
  const float* x    = (const float*)d_in[0];
  const float* Wk   = (const float*)d_in[1];
  const float* Wv   = (const float*)d_in[2];
  const float* Wq   = (const float*)d_in[3];
  const float* Wout = (const float*)d_in[4];
  const float* Wgd  = (const float*)d_in[5];
  const float* bgd  = (const float*)d_in[6];
  const float* Wgl  = (const float*)d_in[7];
  const float* bgl  = (const float*)d_in[8];
  const float* Wgm  = (const float*)d_in[9];
  const float* bgm  = (const float*)d_in[10];
  const float* M1   = (const float*)d_in[11];
  const float* M2   = (const float*)d_in[12];
  const float* S1   = (const float*)d_in[13];
  const float* S2   = (const float*)d_in[14];

  float *k_, *v_, *q_, *z_, *h_, *e_, *dz_, *ret_, *M1n_, *M2n_, *part_;
  cudaGetSymbolAddress((void**)&k_,   g_k);
  cudaGetSymbolAddress((void**)&v_,   g_v);
  cudaGetSymbolAddress((void**)&q_,   g_q);
  cudaGetSymbolAddress((void**)&z_,   g_z);
  cudaGetSymbolAddress((void**)&h_,   g_h);
  cudaGetSymbolAddress((void**)&e_,   g_e);
  cudaGetSymbolAddress((void**)&dz_,  g_dz);
  cudaGetSymbolAddress((void**)&ret_, g_ret);
  cudaGetSymbolAddress((void**)&M1n_, g_M1n);
  cudaGetSymbolAddress((void**)&M2n_, g_M2n);
  cudaGetSymbolAddress((void**)&part_, g_part);

  dim3 t(TPB);
  dim3 gP (DIM / BN, NTOK / BM);   // (8, 128)  N x D outputs
  dim3 gH (HID / BN, NTOK / BM);   // (16, 128) N x H outputs
  dim3 gU1(DIM / BN, HID  / BM);   // (8, 16)   H x D (M1 update)
  dim3 gU2(HID / BN, DIM  / BM);   // (16, 8)   D x H (M2 update)

  // projections: N x D = x @ W^T
  k_gemm_nt<<<gP, t>>>(x, Wk, k_, DIM, DIM, DIM, DIM);
  k_gemm_nt<<<gP, t>>>(x, Wv, v_, DIM, DIM, DIM, DIM);
  k_gemm_nt<<<gP, t>>>(x, Wq, q_, DIM, DIM, DIM, DIM);

  // gates: mean(sigmoid(x @ Wg^T + b))
  k_gemm_gate<<<gP, t>>>(x, Wgd, bgd, part_ + 0 * 1024, DIM, DIM, DIM);
  k_gemm_gate<<<gP, t>>>(x, Wgl, bgl, part_ + 1 * 1024, DIM, DIM, DIM);
  k_gemm_gate<<<gP, t>>>(x, Wgm, bgm, part_ + 2 * 1024, DIM, DIM, DIM);
  k_finalize<<<1, t>>>();

  // memory forward on k: z = k @ M1^T (N x H), h = silu(z)
  k_gemm_silu<<<gH, t>>>(k_, M1, z_, h_, DIM, DIM, DIM, HID);

  // e = (2/D) * (h @ M2^T - v)   (N x D)
  k_gemm_err<<<gP, t>>>(h_, M2, v_, e_, HID, HID, HID, DIM, 2.f / (float)DIM);

  // dz = (e @ M2) * silu'(z)     (N x H, NN)
  k_gemm_dz<<<gH, t>>>(e_, M2, z_, dz_, DIM, DIM, HID, HID);

  // M1n = (1-alpha)M1 + eta*S1 - theta*(dz^T @ k)   (H x D, K = N)
  k_gemm_upd<<<gU1, t>>>(dz_, k_, M1, S1, M1n_, NTOK, HID, DIM, DIM);
  // M2n = (1-alpha)M2 + eta*S2 - theta*(e^T @ h)    (D x H, K = N)
  k_gemm_upd<<<gU2, t>>>(e_, h_, M2, S2, M2n_, NTOK, DIM, HID, HID);

  // retrieval: hq = silu(q @ M1n^T); ret = hq @ M2n^T; out = ret @ Wout^T
  k_gemm_silu<<<gH, t>>>(q_, M1n_, z_, h_, DIM, DIM, DIM, HID);
  k_gemm_nt<<<gP, t>>>(h_, M2n_, ret_, HID, HID, HID, DIM);
  k_gemm_nt<<<gP, t>>>(ret_, Wout, (float*)d_out, DIM, DIM, DIM, DIM);
}

// round 4
// speedup vs baseline: 2.7426x; 2.7426x over previous
#include <cuda_runtime.h>
#include <cuda_bf16.h>
#include <cstdint>

using bf16 = __nv_bfloat16;
constexpr int NTK = 16384, DIMD = 1024, HIDH = 2048;

// ---------------- fp32 scratch ----------------
__device__ float g_kf[(size_t)NTK * DIMD], g_vf[(size_t)NTK * DIMD], g_ef[(size_t)NTK * DIMD];
__device__ float g_zf[(size_t)NTK * HIDH], g_hf[(size_t)NTK * HIDH], g_dzf[(size_t)NTK * HIDH];
__device__ float g_P1[2ull * HIDH * DIMD], g_P2[2ull * DIMD * HIDH];
__device__ float g_part[3 * 1024], g_scal[3];
// ---------------- bf16 hi/lo panels ----------------
__device__ bf16 px_h[(size_t)NTK * DIMD],  px_l[(size_t)NTK * DIMD];
__device__ bf16 pk_h[(size_t)NTK * DIMD],  pk_l[(size_t)NTK * DIMD];
__device__ bf16 pq_h[(size_t)NTK * DIMD],  pq_l[(size_t)NTK * DIMD];
__device__ bf16 pe_h[(size_t)NTK * DIMD],  pe_l[(size_t)NTK * DIMD];
__device__ bf16 ph_h[(size_t)NTK * HIDH],  ph_l[(size_t)NTK * HIDH];
__device__ bf16 pkT_h[(size_t)NTK * DIMD], pkT_l[(size_t)NTK * DIMD];
__device__ bf16 peT_h[(size_t)NTK * DIMD], peT_l[(size_t)NTK * DIMD];
__device__ bf16 phT_h[(size_t)NTK * HIDH], phT_l[(size_t)NTK * HIDH];
__device__ bf16 pdzT_h[(size_t)NTK * HIDH], pdzT_l[(size_t)NTK * HIDH];
__device__ bf16 pW_h[7][DIMD * DIMD], pW_l[7][DIMD * DIMD];
__device__ bf16 pM1_h[HIDH * DIMD],  pM1_l[HIDH * DIMD];
__device__ bf16 pM2_h[DIMD * HIDH],  pM2_l[DIMD * HIDH];
__device__ bf16 pM2T_h[HIDH * DIMD], pM2T_l[HIDH * DIMD];
__device__ bf16 pM1n_h[HIDH * DIMD], pM1n_l[HIDH * DIMD];
__device__ bf16 pM2n_h[DIMD * HIDH], pM2n_l[DIMD * HIDH];

// ---------------- asm helpers (baseline PTX only) ----------------
__device__ __forceinline__ uint32_t s2u(const void* p) {
  uint32_t a;
  asm("{ .reg .u64 t; cvta.to.shared.u64 t, %1; cvt.u32.u64 %0, t; }" : "=r"(a) : "l"(p));
  return a;
}
#define CP16(d, s) asm volatile("cp.async.cg.shared.global [%0],[%1],16;" :: "r"(d), "l"(s))
#define CPC()  asm volatile("cp.async.commit_group;")
#define CPW1() asm volatile("cp.async.wait_group 1;")
#define CPW0() asm volatile("cp.async.wait_group 0;")

__device__ __forceinline__ void ldsm4(uint32_t* r, uint32_t a) {
  asm volatile("ldmatrix.sync.aligned.m8n8.x4.shared.b16 {%0,%1,%2,%3},[%4];"
               : "=r"(r[0]), "=r"(r[1]), "=r"(r[2]), "=r"(r[3]) : "r"(a));
}
__device__ __forceinline__ void mma_(float* c, const uint32_t* a, const uint32_t* b) {
  asm volatile("mma.sync.aligned.m16n8k16.row.col.f32.bf16.bf16.f32 "
               "{%0,%1,%2,%3},{%4,%5,%6,%7},{%8,%9},{%0,%1,%2,%3};"
               : "+f"(c[0]), "+f"(c[1]), "+f"(c[2]), "+f"(c[3])
               : "r"(a[0]), "r"(a[1]), "r"(a[2]), "r"(a[3]), "r"(b[0]), "r"(b[1]));
}
__device__ __forceinline__ uint32_t packbf(float x, float y) {
  __nv_bfloat162 t = __floats2bfloat162_rn(x, y);
  return *(uint32_t*)&t;
}
__device__ __forceinline__ void wpanel(bf16* Ph, bf16* Pl, size_t ix, float x, float y) {
  float hx = __bfloat162float(__float2bfloat16(x));
  float hy = __bfloat162float(__float2bfloat16(y));
  *(uint32_t*)(Ph + ix) = packbf(hx, hy);
  *(uint32_t*)(Pl + ix) = packbf(x - hx, y - hy);
}
__device__ __forceinline__ float sigf(float x) { return 1.f / (1.f + __expf(-x)); }

// ---------------- GEMM: C[128x128] = A(MxK) @ B(NxK)^T, 3-split bf16 ----------------
// smem: per stage {AH,AL,BH,BL} 128 rows x 40 bf16 (80B stride), 10240B each; 2 stages.
// EPI: 0 store  1 silu (Cz=pre-act, C=silu)  2 err: scale*(v-X1)  3 v*silu'(X1)  5 gate
constexpr int SMST = 40960, SMTOT = 81920;

template<int EPI>
__global__ void __launch_bounds__(256, 2)
tc(const bf16* __restrict__ Ah, const bf16* __restrict__ Al,
   const bf16* __restrict__ Bh, const bf16* __restrict__ Bl,
   int lda, int ldb, int nK,
   float* C, float* Cz, bf16* Ph, bf16* Pl, int ldc,
   const float* __restrict__ X1, const float* __restrict__ bias,
   float* partial, float scale)
{
  extern __shared__ __align__(16) char sm[];
  const int tid = threadIdx.x, wid = tid >> 5, lane = tid & 31;
  const size_t m0 = (size_t)blockIdx.y * 128, n0 = (size_t)blockIdx.x * 128;
  const size_t kpos = (size_t)blockIdx.z * nK * 32;
  if (C) C += (size_t)blockIdx.z * gridDim.y * 128 * ldc;
  const uint32_t sb = s2u(sm);
  const int m_w = (wid >> 2) * 64, n_w = (wid & 3) * 32;

  auto loadst = [&](int st, int kc) {
    size_t ao = m0 * lda + kpos + (size_t)kc * 32;
    size_t bo = n0 * ldb + kpos + (size_t)kc * 32;
    uint32_t d = sb + st * SMST;
#pragma unroll
    for (int i = 0; i < 2; ++i) {
      int idx = tid * 2 + i, row = idx >> 2, c16 = idx & 3;
      uint32_t doff = row * 80 + c16 * 16;
      size_t sa = ao + (size_t)row * lda + c16 * 8;
      size_t sbo = bo + (size_t)row * ldb + c16 * 8;
      CP16(d + doff,         Ah + sa);
      CP16(d + 10240 + doff, Al + sa);
      CP16(d + 20480 + doff, Bh + sbo);
      CP16(d + 30720 + doff, Bl + sbo);
    }
  };

  float acc[4][4][4] = {};
  loadst(0, 0); CPC();
  for (int kc = 0; kc < nK; ++kc) {
    if (kc + 1 < nK) { loadst((kc + 1) & 1, kc + 1); CPC(); CPW1(); }
    else CPW0();
    __syncthreads();
    uint32_t base = sb + (kc & 1) * SMST;
#pragma unroll
    for (int k2 = 0; k2 < 2; ++k2) {
      uint32_t aF[4][4], bF[4][2], t4[4];
      uint32_t aRow = base + (m_w + (lane & 15)) * 80 + (lane >> 4) * 16 + k2 * 32;
      uint32_t bRow = base + 20480 + (n_w + (lane & 7) + ((lane >> 4) << 3)) * 80
                    + ((lane >> 3) & 1) * 16 + k2 * 32;
#define LD_A(off) { _Pragma("unroll") for (int mt = 0; mt < 4; ++mt) ldsm4(aF[mt], aRow + (off) + mt * 1280); }
#define LD_B(off) { _Pragma("unroll") for (int np = 0; np < 2; ++np) { ldsm4(t4, bRow + (off) + np * 1280); \
      bF[np*2][0]=t4[0]; bF[np*2][1]=t4[1]; bF[np*2+1][0]=t4[2]; bF[np*2+1][1]=t4[3]; } }
#define MMALL { _Pragma("unroll") for (int mt = 0; mt < 4; ++mt) _Pragma("unroll") for (int nt = 0; nt < 4; ++nt) \
      mma_(acc[mt][nt], aF[mt], bF[nt]); }
      LD_A(0);     LD_B(0);     MMALL;   // Ah*Bh
      LD_B(10240); MMALL;                // Ah*Bl
      LD_A(10240); LD_B(0); MMALL;       // Al*Bh
#undef LD_A
#undef LD_B
#undef MMALL
    }
    __syncthreads();
  }

  // ---- epilogue ----
  if (EPI == 5) {
    float s = 0.f;
#pragma unroll
    for (int mt = 0; mt < 4; ++mt)
#pragma unroll
      for (int nt = 0; nt < 4; ++nt) {
        size_t cg = n0 + n_w + nt * 8 + ((lane & 3) << 1);
        float b0 = __ldg(bias + cg), b1 = __ldg(bias + cg + 1);
        float* ac = acc[mt][nt];
        s += sigf(ac[0] + b0) + sigf(ac[1] + b1) + sigf(ac[2] + b0) + sigf(ac[3] + b1);
      }
    float* red = (float*)sm;
    red[tid] = s; __syncthreads();
    for (int o = 128; o > 0; o >>= 1) {
      if (tid < o) red[tid] += red[tid + o];
      __syncthreads();
    }
    if (tid == 0) partial[blockIdx.y * gridDim.x + blockIdx.x] = red[0];
    return;
  }
#pragma unroll
  for (int mt = 0; mt < 4; ++mt)
#pragma unroll
    for (int nt = 0; nt < 4; ++nt) {
      size_t rg = m0 + m_w + mt * 16 + (lane >> 2);
      size_t cg = n0 + n_w + nt * 8 + ((lane & 3) << 1);
      float* ac = acc[mt][nt];
#pragma unroll
      for (int h2 = 0; h2 < 2; ++h2) {
        size_t ix = (rg + h2 * 8) * (size_t)ldc + cg;
        float v0 = ac[h2 * 2], v1 = ac[h2 * 2 + 1];
        if (EPI == 1) {
          if (Cz) *(float2*)(Cz + ix) = make_float2(v0, v1);
          v0 = v0 * sigf(v0); v1 = v1 * sigf(v1);
        } else if (EPI == 2) {
          float2 vv = *(const float2*)(X1 + ix);
          v0 = scale * (v0 - vv.x); v1 = scale * (v1 - vv.y);
        } else if (EPI == 3) {
          float2 zz = *(const float2*)(X1 + ix);
          float s0 = sigf(zz.x), s1 = sigf(zz.y);
          v0 *= s0 * (1.f + zz.x * (1.f - s0));
          v1 *= s1 * (1.f + zz.y * (1.f - s1));
        }
        if (C) *(float2*)(C + ix) = make_float2(v0, v1);
        if (Ph) wpanel(Ph, Pl, ix, v0, v1);
      }
    }
}

// ---------------- split: fp32 [n8*8] -> bf16 hi/lo (row-major, same layout) ----------------
__global__ void k_split(const float* __restrict__ src, bf16* __restrict__ hi,
                        bf16* __restrict__ lo, size_t n8)
{
  for (size_t t = (size_t)blockIdx.x * blockDim.x + threadIdx.x; t < n8;
       t += (size_t)gridDim.x * blockDim.x) {
    size_t i = t * 8;
    float4 a = *(const float4*)(src + i), b = *(const float4*)(src + i + 4);
    float v[8] = {a.x, a.y, a.z, a.w, b.x, b.y, b.z, b.w};
    uint32_t H[4], L[4];
#pragma unroll
    for (int j = 0; j < 4; ++j) {
      float h0 = __bfloat162float(__float2bfloat16(v[2*j]));
      float h1 = __bfloat162float(__float2bfloat16(v[2*j+1]));
      H[j] = packbf(h0, h1); L[j] = packbf(v[2*j] - h0, v[2*j+1] - h1);
    }
    *(uint4*)(hi + i) = *(uint4*)H;
    *(uint4*)(lo + i) = *(uint4*)L;
  }
}

// transpose-split: fp32 src [R x C] -> bf16 hi/lo [C x R]
__global__ void k_split_t(const float* __restrict__ src, bf16* __restrict__ hi,
                          bf16* __restrict__ lo, int R, int C)
{
  __shared__ float tile[64][65];
  const int tid = threadIdx.x;
  const size_t r0 = (size_t)blockIdx.y * 64, c0 = (size_t)blockIdx.x * 64;
  const int lr = tid >> 4, lc = (tid & 15) << 2;
#pragma unroll
  for (int i = 0; i < 4; ++i) {
    int rr = lr + i * 16;
    float4 v = *(const float4*)(src + (r0 + rr) * C + c0 + lc);
    tile[rr][lc] = v.x; tile[rr][lc+1] = v.y; tile[rr][lc+2] = v.z; tile[rr][lc+3] = v.w;
  }
  __syncthreads();
#pragma unroll
  for (int p = 0; p < 2; ++p) {
    int task = tid + p * 256;
    int rpl = task >> 3, kl = (task & 7) << 3;
    uint32_t H[4], L[4];
#pragma unroll
    for (int j = 0; j < 4; ++j) {
      float x = tile[kl + 2*j][rpl], y = tile[kl + 2*j + 1][rpl];
      float hx = __bfloat162float(__float2bfloat16(x));
      float hy = __bfloat162float(__float2bfloat16(y));
      H[j] = packbf(hx, hy); L[j] = packbf(x - hx, y - hy);
    }
    size_t off = (c0 + rpl) * (size_t)R + r0 + kl;
    *(uint4*)(hi + off) = *(uint4*)H;
    *(uint4*)(lo + off) = *(uint4*)L;
  }
}

// combine split-K partials + momentum/decay update -> bf16 panels
__global__ void k_upd(const float* __restrict__ P, const float* __restrict__ M,
                      const float* __restrict__ S, bf16* __restrict__ hi,
                      bf16* __restrict__ lo, size_t n8, size_t half)
{
  float al = g_scal[0], th = g_scal[1], et = g_scal[2];
  for (size_t t = (size_t)blockIdx.x * blockDim.x + threadIdx.x; t < n8;
       t += (size_t)gridDim.x * blockDim.x) {
    size_t i = t * 8;
    uint32_t H[4], L[4];
#pragma unroll
    for (int j = 0; j < 4; ++j) {
      size_t i0 = i + 2*j, i1 = i0 + 1;
      float x = (1.f - al) * M[i0] + et * S[i0] - th * (P[i0] + P[half + i0]);
      float y = (1.f - al) * M[i1] + et * S[i1] - th * (P[i1] + P[half + i1]);
      float hx = __bfloat162float(__float2bfloat16(x));
      float hy = __bfloat162float(__float2bfloat16(y));
      H[j] = packbf(hx, hy); L[j] = packbf(x - hx, y - hy);
    }
    *(uint4*)(hi + i) = *(uint4*)H;
    *(uint4*)(lo + i) = *(uint4*)L;
  }
}

__global__ void __launch_bounds__(256) k_fin()
{
  __shared__ float red[256];
  for (int g = 0; g < 3; ++g) {
    float s = 0.f;
    for (int i = threadIdx.x; i < 1024; i += 256) s += g_part[g * 1024 + i];
    red[threadIdx.x] = s; __syncthreads();
    for (int o = 128; o > 0; o >>= 1) {
      if (threadIdx.x < o) red[threadIdx.x] += red[threadIdx.x + o];
      __syncthreads();
    }
    if (threadIdx.x == 0) g_scal[g] = red[0] * (1.f / ((float)NTK * (float)DIMD));
    __syncthreads();
  }
}

// ---------------- host ----------------
template<class T> static float* df(T& s) { void* p = 0; cudaGetSymbolAddress(&p, s); return (float*)p; }
template<class T> static bf16*  db(T& s) { void* p = 0; cudaGetSymbolAddress(&p, s); return (bf16*)p; }

extern "C" void kernel_launch(void* const* d_in, const int* in_sizes, int n_in,
                              void* d_out, int out_size)
{
  (void)in_sizes; (void)n_in; (void)out_size;
  const float* x = (const float*)d_in[0];
  const float* Ws[7] = {(const float*)d_in[1], (const float*)d_in[2], (const float*)d_in[3],
                        (const float*)d_in[4], (const float*)d_in[5], (const float*)d_in[7],
                        (const float*)d_in[9]}; // Wk Wv Wq Wout Wgd Wgl Wgm
  const float* bias[3] = {(const float*)d_in[6], (const float*)d_in[8], (const float*)d_in[10]};
  const float* M1 = (const float*)d_in[11];
  const float* M2 = (const float*)d_in[12];
  const float* S1 = (const float*)d_in[13];
  const float* S2 = (const float*)d_in[14];

  float *kf = df(g_kf), *vf = df(g_vf), *ef = df(g_ef);
  float *zf = df(g_zf), *hf = df(g_hf), *dzf = df(g_dzf);
  float *P1 = df(g_P1), *P2 = df(g_P2), *part = df(g_part);
  bf16 *pxh = db(px_h), *pxl = db(px_l), *pkh = db(pk_h), *pkl = db(pk_l);
  bf16 *pqh = db(pq_h), *pql = db(pq_l), *peh = db(pe_h), *pel = db(pe_l);
  bf16 *phh = db(ph_h), *phl = db(ph_l);
  bf16 *pkTh = db(pkT_h), *pkTl = db(pkT_l), *peTh = db(peT_h), *peTl = db(peT_l);
  bf16 *phTh = db(phT_h), *phTl = db(phT_l), *pdzTh = db(pdzT_h), *pdzTl = db(pdzT_l);
  bf16 *pWh = db(pW_h), *pWl = db(pW_l);
  bf16 *pM1h = db(pM1_h), *pM1l = db(pM1_l), *pM2h = db(pM2_h), *pM2l = db(pM2_l);
  bf16 *pM2Th = db(pM2T_h), *pM2Tl = db(pM2T_l);
  bf16 *pM1nh = db(pM1n_h), *pM1nl = db(pM1n_l), *pM2nh = db(pM2n_h), *pM2nl = db(pM2n_l);

  cudaFuncSetAttribute(tc<0>, cudaFuncAttributeMaxDynamicSharedMemorySize, SMTOT);
  cudaFuncSetAttribute(tc<1>, cudaFuncAttributeMaxDynamicSharedMemorySize, SMTOT);
  cudaFuncSetAttribute(tc<2>, cudaFuncAttributeMaxDynamicSharedMemorySize, SMTOT);
  cudaFuncSetAttribute(tc<3>, cudaFuncAttributeMaxDynamicSharedMemorySize, SMTOT);
  cudaFuncSetAttribute(tc<5>, cudaFuncAttributeMaxDynamicSharedMemorySize, SMTOT);

  const int T = 256;
  float* nf = nullptr; bf16* nb = nullptr;
  const size_t WDD = (size_t)DIMD * DIMD;

  // input splits
  k_split<<<2048, T>>>(x, pxh, pxl, (size_t)NTK * DIMD / 8);
  for (int i = 0; i < 7; ++i)
    k_split<<<512, T>>>(Ws[i], pWh + i * WDD, pWl + i * WDD, WDD / 8);
  k_split<<<512, T>>>(M1, pM1h, pM1l, (size_t)HIDH * DIMD / 8);
  k_split<<<512, T>>>(M2, pM2h, pM2l, (size_t)DIMD * HIDH / 8);
  k_split_t<<<dim3(HIDH / 64, DIMD / 64), T>>>(M2, pM2Th, pM2Tl, DIMD, HIDH);

  // projections
  tc<0><<<dim3(8, 128), T, SMTOT>>>(pxh, pxl, pWh + 0 * WDD, pWl + 0 * WDD, DIMD, DIMD, 32,
                                    kf, nf, pkh, pkl, DIMD, nf, nf, nf, 0.f);
  tc<0><<<dim3(8, 128), T, SMTOT>>>(pxh, pxl, pWh + 1 * WDD, pWl + 1 * WDD, DIMD, DIMD, 32,
                                    vf, nf, nb, nb, DIMD, nf, nf, nf, 0.f);
  tc<0><<<dim3(8, 128), T, SMTOT>>>(pxh, pxl, pWh + 2 * WDD, pWl + 2 * WDD, DIMD, DIMD, 32,
                                    nf, nf, pqh, pql, DIMD, nf, nf, nf, 0.f);
  // gates
  for (int g = 0; g < 3; ++g)
    tc<5><<<dim3(8, 128), T, SMTOT>>>(pxh, pxl, pWh + (4 + g) * WDD, pWl + (4 + g) * WDD,
                                      DIMD, DIMD, 32, nf, nf, nb, nb, DIMD,
                                      nf, bias[g], part + g * 1024, 0.f);
  k_fin<<<1, T>>>();
  k_split_t<<<dim3(DIMD / 64, NTK / 64), T>>>(kf, pkTh, pkTl, NTK, DIMD);

  // z = k @ M1^T, h = silu(z)
  tc<1><<<dim3(16, 128), T, SMTOT>>>(pkh, pkl, pM1h, pM1l, DIMD, DIMD, 32,
                                     hf, zf, phh, phl, HIDH, nf, nf, nf, 0.f);
  k_split_t<<<dim3(HIDH / 64, NTK / 64), T>>>(hf, phTh, phTl, NTK, HIDH);

  // e = (2/D)(h @ M2^T - v)
  tc<2><<<dim3(8, 128), T, SMTOT>>>(phh, phl, pM2h, pM2l, HIDH, HIDH, 64,
                                    ef, nf, peh, pel, DIMD, vf, nf, nf, 2.f / (float)DIMD);
  k_split_t<<<dim3(DIMD / 64, NTK / 64), T>>>(ef, peTh, peTl, NTK, DIMD);

  // dz = (e @ M2) * silu'(z)
  tc<3><<<dim3(16, 128), T, SMTOT>>>(peh, pel, pM2Th, pM2Tl, DIMD, DIMD, 32,
                                     dzf, nf, nb, nb, HIDH, zf, nf, nf, 0.f);
  k_split_t<<<dim3(HIDH / 64, NTK / 64), T>>>(dzf, pdzTh, pdzTl, NTK, HIDH);

  // weight-grad GEMMs (split-K=2) + fused update into panels
  tc<0><<<dim3(8, 16, 2), T, SMTOT>>>(pdzTh, pdzTl, pkTh, pkTl, NTK, NTK, 256,
                                      P1, nf, nb, nb, DIMD, nf, nf, nf, 0.f);
  tc<0><<<dim3(16, 8, 2), T, SMTOT>>>(peTh, peTl, phTh, phTl, NTK, NTK, 256,
                                      P2, nf, nb, nb, HIDH, nf, nf, nf, 0.f);
  k_upd<<<512, T>>>(P1, M1, S1, pM1nh, pM1nl, (size_t)HIDH * DIMD / 8, (size_t)HIDH * DIMD);
  k_upd<<<512, T>>>(P2, M2, S2, pM2nh, pM2nl, (size_t)DIMD * HIDH / 8, (size_t)DIMD * HIDH);

  // retrieval
  tc<1><<<dim3(16, 128), T, SMTOT>>>(pqh, pql, pM1nh, pM1nl, DIMD, DIMD, 32,
                                     nf, nf, phh, phl, HIDH, nf, nf, nf, 0.f);
  tc<0><<<dim3(8, 128), T, SMTOT>>>(phh, phl, pM2nh, pM2nl, HIDH, HIDH, 64,
                                    nf, nf, peh, pel, DIMD, nf, nf, nf, 0.f);
  tc<0><<<dim3(8, 128), T, SMTOT>>>(peh, pel, pWh + 3 * WDD, pWl + 3 * WDD, DIMD, DIMD, 32,
                                    (float*)d_out, nf, nb, nb, DIMD, nf, nf, nf, 0.f);
}